// round 2
// baseline (speedup 1.0000x reference)
#include <cuda_runtime.h>
#include <math.h>

// Problem dims
#define T_  4
#define B_  32
#define C_  256
#define N_  1024     // H*W
#define EPS_ 1e-5f

// Scratch (allocation-free rule: __device__ globals)
__device__ float g_qlin[T_ * B_ * C_ * N_];   // 134 MB
__device__ float g_klin[T_ * B_ * C_ * N_];   // 134 MB
__device__ float g_xone[T_ * B_ * C_ * N_];   // 134 MB

// ---------------------------------------------------------------------------
// K1: batched GEMM (M=128-tile of 256, N=128-tile of 1024, K=256) + BN
//     grid: (ntile=8, {q0,q1,k0,k1}=4, batch=128), 256 threads, 8x8/thread
// ---------------------------------------------------------------------------
__global__ void __launch_bounds__(256) gemm_qk_kernel(
    const float* __restrict__ x,
    const float* __restrict__ q_w, const float* __restrict__ q_g,
    const float* __restrict__ q_be, const float* __restrict__ q_m,
    const float* __restrict__ q_v,
    const float* __restrict__ k_w, const float* __restrict__ k_g,
    const float* __restrict__ k_be, const float* __restrict__ k_m,
    const float* __restrict__ k_v)
{
    __shared__ float As[16][128];   // transposed weight tile: As[k][m]
    __shared__ float Bs[16][128];   // x tile: Bs[k][n]

    const int tid   = threadIdx.x;
    const int ntile = blockIdx.x;            // 0..7
    const int which = blockIdx.y >> 1;       // 0=q, 1=k
    const int obase = (blockIdx.y & 1) * 128;
    const int batch = blockIdx.z;            // t*B + b

    const float* w  = which ? k_w  : q_w;
    const float* gg = which ? k_g  : q_g;
    const float* bb = which ? k_be : q_be;
    const float* mm = which ? k_m  : q_m;
    const float* vv = which ? k_v  : q_v;
    float* outp     = which ? g_klin : g_qlin;

    const float* xb = x + (size_t)batch * C_ * N_ + ntile * 128;

    const int tx = tid & 15;   // col group: cols tx*4 and 64+tx*4
    const int ty = tid >> 4;   // row group: rows ty*4 and 64+ty*4

    float acc[2][2][4][4];
    #pragma unroll
    for (int a = 0; a < 2; ++a)
        #pragma unroll
        for (int bq = 0; bq < 2; ++bq)
            #pragma unroll
            for (int i = 0; i < 4; ++i)
                #pragma unroll
                for (int j = 0; j < 4; ++j)
                    acc[a][bq][i][j] = 0.0f;

    for (int kk = 0; kk < C_; kk += 16) {
        // load A tile (128 rows x 16 k), transpose into As[k][m]
        #pragma unroll
        for (int l = 0; l < 2; ++l) {
            int idx = tid + l * 256;      // 0..511 float4s
            int row = idx >> 2;           // 0..127
            int c4  = (idx & 3) * 4;      // 0,4,8,12
            float4 a = *(const float4*)(w + (size_t)(obase + row) * C_ + kk + c4);
            As[c4 + 0][row] = a.x;
            As[c4 + 1][row] = a.y;
            As[c4 + 2][row] = a.z;
            As[c4 + 3][row] = a.w;
        }
        // load B tile (16 k x 128 n)
        #pragma unroll
        for (int l = 0; l < 2; ++l) {
            int idx = tid + l * 256;
            int kr  = idx >> 5;           // 0..15
            int n4  = idx & 31;           // 0..31
            float4 bvec = *(const float4*)(xb + (size_t)(kk + kr) * N_ + n4 * 4);
            *(((float4*)&Bs[kr][0]) + n4) = bvec;
        }
        __syncthreads();

        #pragma unroll
        for (int k = 0; k < 16; ++k) {
            float4 a0 = *(const float4*)&As[k][ty * 4];
            float4 a1 = *(const float4*)&As[k][64 + ty * 4];
            float4 b0 = *(const float4*)&Bs[k][tx * 4];
            float4 b1 = *(const float4*)&Bs[k][64 + tx * 4];
            float av[2][4] = {{a0.x, a0.y, a0.z, a0.w}, {a1.x, a1.y, a1.z, a1.w}};
            float bv[2][4] = {{b0.x, b0.y, b0.z, b0.w}, {b1.x, b1.y, b1.z, b1.w}};
            #pragma unroll
            for (int ih = 0; ih < 2; ++ih)
                #pragma unroll
                for (int jh = 0; jh < 2; ++jh)
                    #pragma unroll
                    for (int i = 0; i < 4; ++i)
                        #pragma unroll
                        for (int j = 0; j < 4; ++j)
                            acc[ih][jh][i][j] += av[ih][i] * bv[jh][j];
        }
        __syncthreads();
    }

    // epilogue: BN (y*inv + (beta - mean*inv)) and store
    #pragma unroll
    for (int ih = 0; ih < 2; ++ih)
        #pragma unroll
        for (int i = 0; i < 4; ++i) {
            int o = obase + ih * 64 + ty * 4 + i;
            float inv = gg[o] / sqrtf(vv[o] + EPS_);
            float sh  = bb[o] - mm[o] * inv;
            float* orow = outp + ((size_t)batch * C_ + o) * N_ + ntile * 128;
            #pragma unroll
            for (int jh = 0; jh < 2; ++jh) {
                float4 r;
                r.x = acc[ih][jh][i][0] * inv + sh;
                r.y = acc[ih][jh][i][1] * inv + sh;
                r.z = acc[ih][jh][i][2] * inv + sh;
                r.w = acc[ih][jh][i][3] * inv + sh;
                *(float4*)(orow + jh * 64 + tx * 4) = r;
            }
        }
}

// ---------------------------------------------------------------------------
// K2: fused q-LIF, k-LIF, head channel-sum, attn-LIF (v_th=0.5), gating.
//     One thread owns one (b, head, n) and all dh=32 channels; time recurrence
//     entirely in registers. grid: (N/256=4, heads=8, B=32), 256 threads.
// ---------------------------------------------------------------------------
__global__ void __launch_bounds__(256) lif_attn_kernel()
{
    const int n = blockIdx.x * 256 + threadIdx.x;  // 0..1023
    const int h = blockIdx.y;                      // 0..7
    const int b = blockIdx.z;                      // 0..31

    float vq[32], vk[32];
    #pragma unroll
    for (int d = 0; d < 32; ++d) { vq[d] = 0.0f; vk[d] = 0.0f; }
    float va = 0.0f;

    #pragma unroll
    for (int t = 0; t < T_; ++t) {
        size_t base = ((size_t)(t * B_ + b) * C_ + h * 32) * N_ + n;
        float qs = 0.0f;
        unsigned kmask = 0u;
        #pragma unroll
        for (int d = 0; d < 32; ++d) {
            float q  = g_qlin[base + (size_t)d * N_];
            float v1 = vq[d] + (q - vq[d]) * 0.5f;
            bool  sq = (v1 >= 1.0f);
            qs += sq ? 1.0f : 0.0f;
            vq[d] = sq ? 0.0f : v1;

            float kx = g_klin[base + (size_t)d * N_];
            float v2 = vk[d] + (kx - vk[d]) * 0.5f;
            bool  sk = (v2 >= 1.0f);
            if (sk) kmask |= (1u << d);
            vk[d] = sk ? 0.0f : v2;
        }
        float va1 = va + (qs - va) * 0.5f;
        bool  sa  = (va1 >= 0.5f);
        va = sa ? 0.0f : va1;
        float am = sa ? 1.0f : 0.0f;
        #pragma unroll
        for (int d = 0; d < 32; ++d)
            g_xone[base + (size_t)d * N_] = ((kmask >> d) & 1u) ? am : 0.0f;
    }
}

// ---------------------------------------------------------------------------
// K3: projection GEMM (+bias, +BN) fused with final LIF over T.
//     Block owns a 128x64 (o x n) tile for one b, loops t with membrane
//     state in registers. grid: (N/64=16, 2, B=32), 256 threads, 8x4/thread.
// ---------------------------------------------------------------------------
__global__ void __launch_bounds__(256) proj_lif_kernel(
    const float* __restrict__ p_w, const float* __restrict__ p_b,
    const float* __restrict__ p_g, const float* __restrict__ p_be,
    const float* __restrict__ p_m, const float* __restrict__ p_v,
    float* __restrict__ out)
{
    __shared__ float As[16][128];
    __shared__ float Bs[16][64];

    const int tid   = threadIdx.x;
    const int ntile = blockIdx.x;        // 0..15
    const int obase = blockIdx.y * 128;  // 0 or 128
    const int b     = blockIdx.z;        // 0..31
    const int tx = tid & 15;             // cols tx*4..tx*4+3
    const int ty = tid >> 4;             // rows ty*4 and 64+ty*4

    float inv[2][4], sh[2][4], bias[2][4];
    #pragma unroll
    for (int ih = 0; ih < 2; ++ih)
        #pragma unroll
        for (int i = 0; i < 4; ++i) {
            int o = obase + ih * 64 + ty * 4 + i;
            float iv = p_g[o] / sqrtf(p_v[o] + EPS_);
            inv[ih][i]  = iv;
            sh[ih][i]   = p_be[o] - p_m[o] * iv;
            bias[ih][i] = p_b[o];
        }

    float vmem[2][4][4];
    #pragma unroll
    for (int ih = 0; ih < 2; ++ih)
        #pragma unroll
        for (int i = 0; i < 4; ++i)
            #pragma unroll
            for (int j = 0; j < 4; ++j)
                vmem[ih][i][j] = 0.0f;

    for (int t = 0; t < T_; ++t) {
        float acc[2][4][4];
        #pragma unroll
        for (int ih = 0; ih < 2; ++ih)
            #pragma unroll
            for (int i = 0; i < 4; ++i)
                #pragma unroll
                for (int j = 0; j < 4; ++j)
                    acc[ih][i][j] = 0.0f;

        const float* xb = g_xone + (size_t)(t * B_ + b) * C_ * N_ + ntile * 64;

        for (int kk = 0; kk < C_; kk += 16) {
            #pragma unroll
            for (int l = 0; l < 2; ++l) {
                int idx = tid + l * 256;
                int row = idx >> 2;
                int c4  = (idx & 3) * 4;
                float4 a = *(const float4*)(p_w + (size_t)(obase + row) * C_ + kk + c4);
                As[c4 + 0][row] = a.x;
                As[c4 + 1][row] = a.y;
                As[c4 + 2][row] = a.z;
                As[c4 + 3][row] = a.w;
            }
            {
                int kr = tid >> 4;    // 0..15
                int n4 = tid & 15;    // 0..15
                float4 bvec = *(const float4*)(xb + (size_t)(kk + kr) * N_ + n4 * 4);
                *(((float4*)&Bs[kr][0]) + n4) = bvec;
            }
            __syncthreads();

            #pragma unroll
            for (int k = 0; k < 16; ++k) {
                float4 a0 = *(const float4*)&As[k][ty * 4];
                float4 a1 = *(const float4*)&As[k][64 + ty * 4];
                float4 b0 = *(const float4*)&Bs[k][tx * 4];
                float av[2][4] = {{a0.x, a0.y, a0.z, a0.w}, {a1.x, a1.y, a1.z, a1.w}};
                float bv[4]    = {b0.x, b0.y, b0.z, b0.w};
                #pragma unroll
                for (int ih = 0; ih < 2; ++ih)
                    #pragma unroll
                    for (int i = 0; i < 4; ++i)
                        #pragma unroll
                        for (int j = 0; j < 4; ++j)
                            acc[ih][i][j] += av[ih][i] * bv[j];
            }
            __syncthreads();
        }

        // epilogue: +bias, BN, LIF step, write spikes
        #pragma unroll
        for (int ih = 0; ih < 2; ++ih)
            #pragma unroll
            for (int i = 0; i < 4; ++i) {
                int o = obase + ih * 64 + ty * 4 + i;
                float rr[4];
                #pragma unroll
                for (int j = 0; j < 4; ++j) {
                    float y  = acc[ih][i][j] + bias[ih][i];
                    y = y * inv[ih][i] + sh[ih][i];
                    float v1 = vmem[ih][i][j] + (y - vmem[ih][i][j]) * 0.5f;
                    bool  s  = (v1 >= 1.0f);
                    vmem[ih][i][j] = s ? 0.0f : v1;
                    rr[j] = s ? 1.0f : 0.0f;
                }
                float4 r = make_float4(rr[0], rr[1], rr[2], rr[3]);
                *(float4*)(out + ((size_t)(t * B_ + b) * C_ + o) * N_ + ntile * 64 + tx * 4) = r;
            }
    }
}

// ---------------------------------------------------------------------------
extern "C" void kernel_launch(void* const* d_in, const int* in_sizes, int n_in,
                              void* d_out, int out_size)
{
    (void)in_sizes; (void)n_in; (void)out_size;
    const float* x    = (const float*)d_in[0];
    const float* q_w  = (const float*)d_in[1];
    const float* q_g  = (const float*)d_in[2];
    const float* q_be = (const float*)d_in[3];
    const float* q_m  = (const float*)d_in[4];
    const float* q_v  = (const float*)d_in[5];
    const float* k_w  = (const float*)d_in[6];
    const float* k_g  = (const float*)d_in[7];
    const float* k_be = (const float*)d_in[8];
    const float* k_m  = (const float*)d_in[9];
    const float* k_v  = (const float*)d_in[10];
    const float* p_w  = (const float*)d_in[11];
    const float* p_b  = (const float*)d_in[12];
    const float* p_g  = (const float*)d_in[13];
    const float* p_be = (const float*)d_in[14];
    const float* p_m  = (const float*)d_in[15];
    const float* p_v  = (const float*)d_in[16];
    float* out = (float*)d_out;

    dim3 g1(8, 4, T_ * B_);
    gemm_qk_kernel<<<g1, 256>>>(x, q_w, q_g, q_be, q_m, q_v,
                                k_w, k_g, k_be, k_m, k_v);

    dim3 g2(N_ / 256, 8, B_);
    lif_attn_kernel<<<g2, 256>>>();

    dim3 g3(N_ / 64, 2, B_);
    proj_lif_kernel<<<g3, 256>>>(p_w, p_b, p_g, p_be, p_m, p_v, out);
}

// round 3
// speedup vs baseline: 1.7087x; 1.7087x over previous
#include <cuda_runtime.h>
#include <math.h>

typedef unsigned long long ull;

// Problem dims
#define T_  4
#define B_  32
#define C_  256
#define N_  1024     // H*W
#define EPS_ 1e-5f

// Scratch (allocation-free rule: __device__ globals)
__device__ float g_qlin[T_ * B_ * C_ * N_];
__device__ float g_klin[T_ * B_ * C_ * N_];
__device__ float g_xone[T_ * B_ * C_ * N_];

// ---- f32x2 helpers (sm_100+: packed dual-fp32 FMA, bit-identical to scalar) ----
__device__ __forceinline__ ull dup2(float a) {
    ull r;
    asm("mov.b64 %0, {%1, %1};" : "=l"(r) : "r"(__float_as_uint(a)));
    return r;
}
__device__ __forceinline__ void ffma2(ull& acc, ull a, ull b) {
    asm("fma.rn.f32x2 %0, %1, %2, %0;" : "+l"(acc) : "l"(a), "l"(b));
}
__device__ __forceinline__ void unpack2(ull v, float& lo, float& hi) {
    unsigned x, y;
    asm("mov.b64 {%0, %1}, %2;" : "=r"(x), "=r"(y) : "l"(v));
    lo = __uint_as_float(x);
    hi = __uint_as_float(y);
}

// ---------------------------------------------------------------------------
// K1: batched GEMM (128x128 tile, K=256) + BN. FFMA2 inner product,
//     double-buffered smem, global prefetch. grid: (8, 4, 128), 256 thr.
//     Column-paired accumulators: B pairs free (LDS.64), A dup'd per scalar.
// ---------------------------------------------------------------------------
__global__ void __launch_bounds__(256, 2) gemm_qk_kernel(
    const float* __restrict__ x,
    const float* __restrict__ q_w, const float* __restrict__ q_g,
    const float* __restrict__ q_be, const float* __restrict__ q_m,
    const float* __restrict__ q_v,
    const float* __restrict__ k_w, const float* __restrict__ k_g,
    const float* __restrict__ k_be, const float* __restrict__ k_m,
    const float* __restrict__ k_v)
{
    __shared__ __align__(16) float As[2][16][128];   // As[buf][k][m]
    __shared__ __align__(16) float Bs[2][16][128];   // Bs[buf][k][n]

    const int tid   = threadIdx.x;
    const int ntile = blockIdx.x;            // 0..7
    const int which = blockIdx.y >> 1;       // 0=q, 1=k
    const int obase = (blockIdx.y & 1) * 128;
    const int batch = blockIdx.z;            // t*B + b

    const float* w  = which ? k_w  : q_w;
    const float* gg = which ? k_g  : q_g;
    const float* bb = which ? k_be : q_be;
    const float* mm = which ? k_m  : q_m;
    const float* vv = which ? k_v  : q_v;
    float* outp     = which ? g_klin : g_qlin;

    const float* xb = x + (size_t)batch * C_ * N_ + ntile * 128;

    const int tx = tid & 15;   // col groups: tx*4 and 64+tx*4
    const int ty = tid >> 4;   // row groups: ty*4 and 64+ty*4

    // global-load indexing
    const int rowA = tid >> 2;          // 0..63 (and +64)
    const int c4A  = (tid & 3) * 4;     // 0,4,8,12
    const int krB  = tid >> 5;          // 0..7 (and +8)
    const int n4B  = (tid & 31) * 4;    // 0..124

    float4 pa0, pa1, pb0, pb1;

    // prologue: tile 0 -> regs -> smem[0]
    pa0 = *(const float4*)(w + (size_t)(obase + rowA) * C_ + c4A);
    pa1 = *(const float4*)(w + (size_t)(obase + 64 + rowA) * C_ + c4A);
    pb0 = *(const float4*)(xb + (size_t)krB * N_ + n4B);
    pb1 = *(const float4*)(xb + (size_t)(8 + krB) * N_ + n4B);

    As[0][c4A + 0][rowA] = pa0.x;  As[0][c4A + 1][rowA] = pa0.y;
    As[0][c4A + 2][rowA] = pa0.z;  As[0][c4A + 3][rowA] = pa0.w;
    As[0][c4A + 0][64 + rowA] = pa1.x;  As[0][c4A + 1][64 + rowA] = pa1.y;
    As[0][c4A + 2][64 + rowA] = pa1.z;  As[0][c4A + 3][64 + rowA] = pa1.w;
    *(float4*)&Bs[0][krB][n4B]     = pb0;
    *(float4*)&Bs[0][8 + krB][n4B] = pb1;
    __syncthreads();

    ull acc2[8][4];
    #pragma unroll
    for (int i = 0; i < 8; ++i)
        #pragma unroll
        for (int j = 0; j < 4; ++j)
            acc2[i][j] = 0ULL;

    #pragma unroll 1
    for (int it = 0; it < 16; ++it) {
        const int cur = it & 1;
        if (it < 15) {
            const int kk = (it + 1) * 16;
            pa0 = *(const float4*)(w + (size_t)(obase + rowA) * C_ + kk + c4A);
            pa1 = *(const float4*)(w + (size_t)(obase + 64 + rowA) * C_ + kk + c4A);
            pb0 = *(const float4*)(xb + (size_t)(kk + krB) * N_ + n4B);
            pb1 = *(const float4*)(xb + (size_t)(kk + 8 + krB) * N_ + n4B);
        }

        #pragma unroll
        for (int k = 0; k < 16; ++k) {
            const float* Ak = &As[cur][k][0];
            const float* Bk = &Bs[cur][k][0];
            float4 a0 = *(const float4*)(Ak + ty * 4);
            float4 a1 = *(const float4*)(Ak + 64 + ty * 4);
            ull bp[4];
            bp[0] = *(const ull*)(Bk + tx * 4);
            bp[1] = *(const ull*)(Bk + tx * 4 + 2);
            bp[2] = *(const ull*)(Bk + 64 + tx * 4);
            bp[3] = *(const ull*)(Bk + 64 + tx * 4 + 2);
            float av[8] = {a0.x, a0.y, a0.z, a0.w, a1.x, a1.y, a1.z, a1.w};
            #pragma unroll
            for (int i = 0; i < 8; ++i) {
                ull ad = dup2(av[i]);
                #pragma unroll
                for (int jp = 0; jp < 4; ++jp)
                    ffma2(acc2[i][jp], ad, bp[jp]);
            }
        }

        if (it < 15) {
            const int nb = cur ^ 1;
            As[nb][c4A + 0][rowA] = pa0.x;  As[nb][c4A + 1][rowA] = pa0.y;
            As[nb][c4A + 2][rowA] = pa0.z;  As[nb][c4A + 3][rowA] = pa0.w;
            As[nb][c4A + 0][64 + rowA] = pa1.x;  As[nb][c4A + 1][64 + rowA] = pa1.y;
            As[nb][c4A + 2][64 + rowA] = pa1.z;  As[nb][c4A + 3][64 + rowA] = pa1.w;
            *(float4*)&Bs[nb][krB][n4B]     = pb0;
            *(float4*)&Bs[nb][8 + krB][n4B] = pb1;
            __syncthreads();
        }
    }

    // epilogue: BN and store
    #pragma unroll
    for (int i = 0; i < 8; ++i) {
        const int o = obase + ((i < 4) ? (ty * 4 + i) : (64 + ty * 4 + (i - 4)));
        const float inv = gg[o] / sqrtf(vv[o] + EPS_);
        const float sh  = bb[o] - mm[o] * inv;
        float c0, c1, c2, c3, c4, c5, c6, c7;
        unpack2(acc2[i][0], c0, c1);
        unpack2(acc2[i][1], c2, c3);
        unpack2(acc2[i][2], c4, c5);
        unpack2(acc2[i][3], c6, c7);
        float* orow = outp + ((size_t)batch * C_ + o) * N_ + ntile * 128;
        float4 r0 = make_float4(c0 * inv + sh, c1 * inv + sh, c2 * inv + sh, c3 * inv + sh);
        float4 r1 = make_float4(c4 * inv + sh, c5 * inv + sh, c6 * inv + sh, c7 * inv + sh);
        *(float4*)(orow + tx * 4)      = r0;
        *(float4*)(orow + 64 + tx * 4) = r1;
    }
}

// ---------------------------------------------------------------------------
// K2: fused q-LIF, k-LIF, head channel-sum, attn-LIF (v_th=0.5), gating.
// ---------------------------------------------------------------------------
__global__ void __launch_bounds__(256) lif_attn_kernel()
{
    const int n = blockIdx.x * 256 + threadIdx.x;  // 0..1023
    const int h = blockIdx.y;                      // 0..7
    const int b = blockIdx.z;                      // 0..31

    float vq[32], vk[32];
    #pragma unroll
    for (int d = 0; d < 32; ++d) { vq[d] = 0.0f; vk[d] = 0.0f; }
    float va = 0.0f;

    #pragma unroll
    for (int t = 0; t < T_; ++t) {
        size_t base = ((size_t)(t * B_ + b) * C_ + h * 32) * N_ + n;
        float qs = 0.0f;
        unsigned kmask = 0u;
        #pragma unroll
        for (int d = 0; d < 32; ++d) {
            float q  = g_qlin[base + (size_t)d * N_];
            float v1 = vq[d] + (q - vq[d]) * 0.5f;
            bool  sq = (v1 >= 1.0f);
            qs += sq ? 1.0f : 0.0f;
            vq[d] = sq ? 0.0f : v1;

            float kx = g_klin[base + (size_t)d * N_];
            float v2 = vk[d] + (kx - vk[d]) * 0.5f;
            bool  sk = (v2 >= 1.0f);
            if (sk) kmask |= (1u << d);
            vk[d] = sk ? 0.0f : v2;
        }
        float va1 = va + (qs - va) * 0.5f;
        bool  sa  = (va1 >= 0.5f);
        va = sa ? 0.0f : va1;
        float am = sa ? 1.0f : 0.0f;
        #pragma unroll
        for (int d = 0; d < 32; ++d)
            g_xone[base + (size_t)d * N_] = ((kmask >> d) & 1u) ? am : 0.0f;
    }
}

// ---------------------------------------------------------------------------
// K3: projection GEMM (+bias, +BN) fused with final LIF over T.
//     128x64 tile per block, FFMA2 row-paired accumulators, double-buffered.
//     grid: (16, 2, 32), 256 threads.
// ---------------------------------------------------------------------------
__global__ void __launch_bounds__(256, 2) proj_lif_kernel(
    const float* __restrict__ p_w, const float* __restrict__ p_b,
    const float* __restrict__ p_g, const float* __restrict__ p_be,
    const float* __restrict__ p_m, const float* __restrict__ p_v,
    float* __restrict__ out)
{
    __shared__ __align__(16) float As[2][16][128];
    __shared__ __align__(16) float Bs[2][16][64];

    const int tid   = threadIdx.x;
    const int ntile = blockIdx.x;        // 0..15
    const int obase = blockIdx.y * 128;  // 0 or 128
    const int b     = blockIdx.z;        // 0..31
    const int tx = tid & 15;             // cols tx*4..tx*4+3
    const int ty = tid >> 4;             // rows ty*4.. and 64+ty*4..

    const int rowA = tid >> 2;
    const int c4A  = (tid & 3) * 4;
    const int krB  = tid >> 4;           // 0..15
    const int n4B  = (tid & 15) * 4;     // 0..60

    // per-row constants; row order r: [ty*4+0..3, 64+ty*4+0..3]
    float inv[8], sh[8], bias[8];
    #pragma unroll
    for (int r = 0; r < 8; ++r) {
        const int o = obase + ((r < 4) ? (ty * 4 + r) : (64 + ty * 4 + (r - 4)));
        const float iv = p_g[o] / sqrtf(p_v[o] + EPS_);
        inv[r]  = iv;
        sh[r]   = p_be[o] - p_m[o] * iv;
        bias[r] = p_b[o];
    }

    float vmem[8][4];
    #pragma unroll
    for (int r = 0; r < 8; ++r)
        #pragma unroll
        for (int j = 0; j < 4; ++j)
            vmem[r][j] = 0.0f;

    #pragma unroll 1
    for (int t = 0; t < T_; ++t) {
        const float* xb = g_xone + (size_t)(t * B_ + b) * C_ * N_ + ntile * 64;

        float4 pa0, pa1, pb0;
        pa0 = *(const float4*)(p_w + (size_t)(obase + rowA) * C_ + c4A);
        pa1 = *(const float4*)(p_w + (size_t)(obase + 64 + rowA) * C_ + c4A);
        pb0 = *(const float4*)(xb + (size_t)krB * N_ + n4B);

        As[0][c4A + 0][rowA] = pa0.x;  As[0][c4A + 1][rowA] = pa0.y;
        As[0][c4A + 2][rowA] = pa0.z;  As[0][c4A + 3][rowA] = pa0.w;
        As[0][c4A + 0][64 + rowA] = pa1.x;  As[0][c4A + 1][64 + rowA] = pa1.y;
        As[0][c4A + 2][64 + rowA] = pa1.z;  As[0][c4A + 3][64 + rowA] = pa1.w;
        *(float4*)&Bs[0][krB][n4B] = pb0;
        __syncthreads();

        ull acc2[4][4];   // [row-pair][col]
        #pragma unroll
        for (int rp = 0; rp < 4; ++rp)
            #pragma unroll
            for (int j = 0; j < 4; ++j)
                acc2[rp][j] = 0ULL;

        #pragma unroll 1
        for (int it = 0; it < 16; ++it) {
            const int cur = it & 1;
            if (it < 15) {
                const int kk = (it + 1) * 16;
                pa0 = *(const float4*)(p_w + (size_t)(obase + rowA) * C_ + kk + c4A);
                pa1 = *(const float4*)(p_w + (size_t)(obase + 64 + rowA) * C_ + kk + c4A);
                pb0 = *(const float4*)(xb + (size_t)(kk + krB) * N_ + n4B);
            }

            #pragma unroll
            for (int k = 0; k < 16; ++k) {
                const float* Ak = &As[cur][k][0];
                const float* Bk = &Bs[cur][k][0];
                ull ap[4];
                ap[0] = *(const ull*)(Ak + ty * 4);
                ap[1] = *(const ull*)(Ak + ty * 4 + 2);
                ap[2] = *(const ull*)(Ak + 64 + ty * 4);
                ap[3] = *(const ull*)(Ak + 64 + ty * 4 + 2);
                float4 bv = *(const float4*)(Bk + tx * 4);
                float bvv[4] = {bv.x, bv.y, bv.z, bv.w};
                #pragma unroll
                for (int j = 0; j < 4; ++j) {
                    ull bd = dup2(bvv[j]);
                    #pragma unroll
                    for (int rp = 0; rp < 4; ++rp)
                        ffma2(acc2[rp][j], ap[rp], bd);
                }
            }

            if (it < 15) {
                const int nb = cur ^ 1;
                As[nb][c4A + 0][rowA] = pa0.x;  As[nb][c4A + 1][rowA] = pa0.y;
                As[nb][c4A + 2][rowA] = pa0.z;  As[nb][c4A + 3][rowA] = pa0.w;
                As[nb][c4A + 0][64 + rowA] = pa1.x;  As[nb][c4A + 1][64 + rowA] = pa1.y;
                As[nb][c4A + 2][64 + rowA] = pa1.z;  As[nb][c4A + 3][64 + rowA] = pa1.w;
                *(float4*)&Bs[nb][krB][n4B] = pb0;
                __syncthreads();
            }
        }

        // epilogue: unpack pairs, +bias, BN, LIF step, write spikes
        float res[8][4];
        #pragma unroll
        for (int rp = 0; rp < 4; ++rp)
            #pragma unroll
            for (int j = 0; j < 4; ++j) {
                float ylo, yhi;
                unpack2(acc2[rp][j], ylo, yhi);
                res[rp * 2 + 0][j] = ylo;
                res[rp * 2 + 1][j] = yhi;
            }

        #pragma unroll
        for (int r = 0; r < 8; ++r) {
            const int o = obase + ((r < 4) ? (ty * 4 + r) : (64 + ty * 4 + (r - 4)));
            float rr[4];
            #pragma unroll
            for (int j = 0; j < 4; ++j) {
                float y  = res[r][j] + bias[r];
                y = y * inv[r] + sh[r];
                float v1 = vmem[r][j] + (y - vmem[r][j]) * 0.5f;
                bool  s  = (v1 >= 1.0f);
                vmem[r][j] = s ? 0.0f : v1;
                rr[j] = s ? 1.0f : 0.0f;
            }
            float4 rv = make_float4(rr[0], rr[1], rr[2], rr[3]);
            *(float4*)(out + ((size_t)(t * B_ + b) * C_ + o) * N_ + ntile * 64 + tx * 4) = rv;
        }
        // no extra sync needed: next t's prologue writes buf0, which all
        // threads finished reading before the it=14 sync of this t.
    }
}

// ---------------------------------------------------------------------------
extern "C" void kernel_launch(void* const* d_in, const int* in_sizes, int n_in,
                              void* d_out, int out_size)
{
    (void)in_sizes; (void)n_in; (void)out_size;
    const float* x    = (const float*)d_in[0];
    const float* q_w  = (const float*)d_in[1];
    const float* q_g  = (const float*)d_in[2];
    const float* q_be = (const float*)d_in[3];
    const float* q_m  = (const float*)d_in[4];
    const float* q_v  = (const float*)d_in[5];
    const float* k_w  = (const float*)d_in[6];
    const float* k_g  = (const float*)d_in[7];
    const float* k_be = (const float*)d_in[8];
    const float* k_m  = (const float*)d_in[9];
    const float* k_v  = (const float*)d_in[10];
    const float* p_w  = (const float*)d_in[11];
    const float* p_b  = (const float*)d_in[12];
    const float* p_g  = (const float*)d_in[13];
    const float* p_be = (const float*)d_in[14];
    const float* p_m  = (const float*)d_in[15];
    const float* p_v  = (const float*)d_in[16];
    float* out = (float*)d_out;

    dim3 g1(8, 4, T_ * B_);
    gemm_qk_kernel<<<g1, 256>>>(x, q_w, q_g, q_be, q_m, q_v,
                                k_w, k_g, k_be, k_m, k_v);

    dim3 g2(N_ / 256, 8, B_);
    lif_attn_kernel<<<g2, 256>>>();

    dim3 g3(N_ / 64, 2, B_);
    proj_lif_kernel<<<g3, 256>>>(p_w, p_b, p_g, p_be, p_m, p_v, out);
}

// round 5
// speedup vs baseline: 1.9012x; 1.1126x over previous
#include <cuda_runtime.h>
#include <cuda_bf16.h>
#include <math.h>
#include <cstdint>

// Problem dims
#define T_  4
#define B_  32
#define C_  256
#define N_  1024     // H*W
#define EPS_ 1e-5f
#define NBATCH (T_ * B_)   // 128

// Scratch (allocation-free rule: __device__ globals)
__device__ float g_qlin[NBATCH * C_ * N_];                       // also reused as plin
__device__ float g_klin[NBATCH * C_ * N_];
__device__ __nv_bfloat16 g_xsplit[(size_t)NBATCH * 3 * N_ * C_]; // [batch][part][n][c]
__device__ __nv_bfloat16 g_xoneT[(size_t)NBATCH * N_ * C_];      // [batch][n][c]
__device__ __nv_bfloat16 g_wsplit[3 * 3 * C_ * C_];              // [branch(q,k,p)][part][o][c]

// ---------------- PTX helpers (family-agnostic, sm_80+) ----------------
__device__ __forceinline__ uint32_t smem_u32(const void* p) {
    uint32_t a;
    asm("{ .reg .u64 t; cvta.to.shared.u64 t, %1; cvt.u32.u64 %0, t; }" : "=r"(a) : "l"(p));
    return a;
}
__device__ __forceinline__ void ldsm_x4(uint32_t& r0, uint32_t& r1, uint32_t& r2,
                                        uint32_t& r3, uint32_t addr) {
    asm volatile("ldmatrix.sync.aligned.m8n8.x4.shared.b16 {%0,%1,%2,%3}, [%4];"
                 : "=r"(r0), "=r"(r1), "=r"(r2), "=r"(r3) : "r"(addr));
}
__device__ __forceinline__ void mma_bf16(float* d, const uint32_t* a, const uint32_t* b) {
    asm volatile("mma.sync.aligned.m16n8k16.row.col.f32.bf16.bf16.f32 "
                 "{%0,%1,%2,%3}, {%4,%5,%6,%7}, {%8,%9}, {%0,%1,%2,%3};"
                 : "+f"(d[0]), "+f"(d[1]), "+f"(d[2]), "+f"(d[3])
                 : "r"(a[0]), "r"(a[1]), "r"(a[2]), "r"(a[3]), "r"(b[0]), "r"(b[1]));
}
__device__ __forceinline__ void cpa16(uint32_t saddr, const void* g) {
    asm volatile("cp.async.cg.shared.global [%0], [%1], 16;" :: "r"(saddr), "l"(g) : "memory");
}
#define CP_COMMIT() asm volatile("cp.async.commit_group;" ::: "memory")
#define CP_WAIT1()  asm volatile("cp.async.wait_group 1;" ::: "memory")
#define CP_WAIT0()  asm volatile("cp.async.wait_group 0;" ::: "memory")

// ---------------------------------------------------------------------------
// Split kernels: fp32 -> 3x bf16 (RN split; residuals Sterbenz-exact)
// ---------------------------------------------------------------------------
__device__ __forceinline__ void split3(float v, __nv_bfloat16& h1,
                                       __nv_bfloat16& h2, __nv_bfloat16& h3) {
    h1 = __float2bfloat16(v);
    float r = v - __bfloat162float(h1);
    h2 = __float2bfloat16(r);
    float r2 = r - __bfloat162float(h2);
    h3 = __float2bfloat16(r2);
}

__global__ void __launch_bounds__(256) split_w_kernel(
    const float* __restrict__ q_w, const float* __restrict__ k_w,
    const float* __restrict__ p_w)
{
    int idx = blockIdx.x * 256 + threadIdx.x;
    if (idx >= C_ * C_) return;
    const float* ws[3] = {q_w, k_w, p_w};
    #pragma unroll
    for (int br = 0; br < 3; ++br) {
        __nv_bfloat16 h1, h2, h3;
        split3(ws[br][idx], h1, h2, h3);
        g_wsplit[(br * 3 + 0) * C_ * C_ + idx] = h1;
        g_wsplit[(br * 3 + 1) * C_ * C_ + idx] = h2;
        g_wsplit[(br * 3 + 2) * C_ * C_ + idx] = h3;
    }
}

// x [batch][c][n] -> xsplit [batch][part][n][c]
__global__ void __launch_bounds__(256) split_x_kernel(const float* __restrict__ x)
{
    __shared__ float t[32][129];
    const int nb = blockIdx.x * 128;
    const int cb = blockIdx.y * 32;
    const int batch = blockIdx.z;
    const int tid = threadIdx.x;

    const float* xb = x + ((size_t)batch * C_ + cb) * N_ + nb;
    #pragma unroll
    for (int i = 0; i < 16; ++i) {
        int idx = tid + i * 256;
        int c = idx >> 7, n = idx & 127;
        t[c][n] = xb[(size_t)c * N_ + n];
    }
    __syncthreads();
    size_t ob = ((size_t)batch * 3) * N_ * C_ + (size_t)nb * C_ + cb;
    #pragma unroll
    for (int i = 0; i < 16; ++i) {
        int idx = tid + i * 256;
        int n = idx >> 5, c = idx & 31;
        __nv_bfloat16 h1, h2, h3;
        split3(t[c][n], h1, h2, h3);
        size_t o = ob + (size_t)n * C_ + c;
        g_xsplit[o] = h1;
        g_xsplit[o + (size_t)N_ * C_] = h2;
        g_xsplit[o + (size_t)2 * N_ * C_] = h3;
    }
}

// ---------------------------------------------------------------------------
// K1: Q/K GEMM via mma.sync bf16, 6 split-product segments (K' = 1536) + BN.
// CTA: 128(M) x 128(N), 4 warps of 64x64. grid (ntile=8, branch*2+mhalf=4, 128).
// ---------------------------------------------------------------------------
__global__ void __launch_bounds__(128) hmma_qk_kernel(
    const float* __restrict__ q_g, const float* __restrict__ q_be,
    const float* __restrict__ q_m, const float* __restrict__ q_v,
    const float* __restrict__ k_g, const float* __restrict__ k_be,
    const float* __restrict__ k_m, const float* __restrict__ k_v)
{
    __shared__ __nv_bfloat16 As[2][128][40];   // 32 cols + 16B pad
    __shared__ __nv_bfloat16 Bs[2][128][40];

    const int tid    = threadIdx.x;
    const int lane   = tid & 31;
    const int wid    = tid >> 5;
    const int warp_m = wid >> 1;     // 0..1
    const int warp_n = wid & 1;      // 0..1
    const int ntile  = blockIdx.x;
    const int branch = blockIdx.y >> 1;
    const int mhalf  = blockIdx.y & 1;
    const int batch  = blockIdx.z;

    const __nv_bfloat16* Ab = g_wsplit
        + ((size_t)(branch * 3) * C_ + mhalf * 128) * C_;
    const __nv_bfloat16* Bb = g_xsplit
        + ((size_t)(batch * 3) * N_ + ntile * 128) * C_;

    // loader: thread covers 4 A chunks + 4 B chunks of 16B each
    auto load_tiles = [&](int buf, int seg, int kc) {
        int bp = (seg >= 5) ? 2 : ((seg >= 3) ? 1 : 0);
        int ap = seg - ((bp == 1) ? 3 : ((bp == 2) ? 5 : 0));
        const __nv_bfloat16* Ag = Ab + (size_t)ap * C_ * C_ + kc * 32;
        const __nv_bfloat16* Bg = Bb + (size_t)bp * N_ * C_ + kc * 32;
        #pragma unroll
        for (int i = 0; i < 4; ++i) {
            int cid = tid + i * 128;
            int row = cid >> 2, c8 = (cid & 3) * 8;
            cpa16(smem_u32(&As[buf][row][c8]), Ag + (size_t)row * C_ + c8);
            cpa16(smem_u32(&Bs[buf][row][c8]), Bg + (size_t)row * C_ + c8);
        }
    };

    float acc[4][8][4];
    #pragma unroll
    for (int mt = 0; mt < 4; ++mt)
        #pragma unroll
        for (int nt = 0; nt < 8; ++nt)
            #pragma unroll
            for (int c = 0; c < 4; ++c)
                acc[mt][nt][c] = 0.0f;

    load_tiles(0, 0, 0);
    CP_COMMIT();

    #pragma unroll 1
    for (int it = 0; it < 48; ++it) {
        const int buf = it & 1;
        if (it < 47) {
            load_tiles(buf ^ 1, (it + 1) >> 3, (it + 1) & 7);
            CP_COMMIT();
            CP_WAIT1();
        } else {
            CP_WAIT0();
        }
        __syncthreads();

        #pragma unroll
        for (int ks = 0; ks < 2; ++ks) {
            uint32_t af[4][4];
            #pragma unroll
            for (int mt = 0; mt < 4; ++mt) {
                int arow = warp_m * 64 + mt * 16 + (lane & 15);
                int acol = ks * 16 + (lane >> 4) * 8;
                ldsm_x4(af[mt][0], af[mt][1], af[mt][2], af[mt][3],
                        smem_u32(&As[buf][arow][acol]));
            }
            uint32_t bfr[8][2];
            #pragma unroll
            for (int g = 0; g < 4; ++g) {
                int brow = warp_n * 64 + g * 16 + (lane & 7) + ((lane >> 4) & 1) * 8;
                int bcol = ks * 16 + ((lane >> 3) & 1) * 8;
                uint32_t r0, r1, r2, r3;
                ldsm_x4(r0, r1, r2, r3, smem_u32(&Bs[buf][brow][bcol]));
                bfr[g * 2 + 0][0] = r0;  bfr[g * 2 + 0][1] = r1;
                bfr[g * 2 + 1][0] = r2;  bfr[g * 2 + 1][1] = r3;
            }
            #pragma unroll
            for (int mt = 0; mt < 4; ++mt)
                #pragma unroll
                for (int nt = 0; nt < 8; ++nt)
                    mma_bf16(acc[mt][nt], af[mt], bfr[nt]);
        }
        __syncthreads();
    }

    // epilogue: BN and store
    const float* gg = branch ? k_g  : q_g;
    const float* vv = branch ? k_v  : q_v;
    const float* bb = branch ? k_be : q_be;
    const float* mm = branch ? k_m  : q_m;
    float* outp = branch ? g_klin : g_qlin;

    const int n0 = ntile * 128 + warp_n * 64 + (lane & 3) * 2;
    #pragma unroll
    for (int mt = 0; mt < 4; ++mt) {
        #pragma unroll
        for (int h = 0; h < 2; ++h) {
            const int o = mhalf * 128 + warp_m * 64 + mt * 16 + (lane >> 2) + h * 8;
            const float iv = gg[o] / sqrtf(vv[o] + EPS_);
            const float sh = bb[o] - mm[o] * iv;
            float* orow = outp + ((size_t)batch * C_ + o) * N_;
            #pragma unroll
            for (int nt = 0; nt < 8; ++nt) {
                float2 r;
                r.x = acc[mt][nt][h * 2 + 0] * iv + sh;
                r.y = acc[mt][nt][h * 2 + 1] * iv + sh;
                *(float2*)(orow + n0 + nt * 8) = r;
            }
        }
    }
}

// ---------------------------------------------------------------------------
// K2: fused q-LIF, k-LIF, head channel-sum, attn-LIF (v_th=0.5), gating.
// Writes x_one transposed as bf16 [batch][n][c] for the HMMA projection.
// ---------------------------------------------------------------------------
__global__ void __launch_bounds__(256) lif_attn_kernel()
{
    const int n = blockIdx.x * 256 + threadIdx.x;
    const int h = blockIdx.y;
    const int b = blockIdx.z;

    float vq[32], vk[32];
    #pragma unroll
    for (int d = 0; d < 32; ++d) { vq[d] = 0.0f; vk[d] = 0.0f; }
    float va = 0.0f;

    #pragma unroll
    for (int t = 0; t < T_; ++t) {
        size_t base = ((size_t)(t * B_ + b) * C_ + h * 32) * N_ + n;
        float qs = 0.0f;
        unsigned kmask = 0u;
        #pragma unroll
        for (int d = 0; d < 32; ++d) {
            float q  = g_qlin[base + (size_t)d * N_];
            float v1 = vq[d] + (q - vq[d]) * 0.5f;
            bool  sq = (v1 >= 1.0f);
            qs += sq ? 1.0f : 0.0f;
            vq[d] = sq ? 0.0f : v1;

            float kx = g_klin[base + (size_t)d * N_];
            float v2 = vk[d] + (kx - vk[d]) * 0.5f;
            bool  sk = (v2 >= 1.0f);
            if (sk) kmask |= (1u << d);
            vk[d] = sk ? 0.0f : v2;
        }
        float va1 = va + (qs - va) * 0.5f;
        bool  sa  = (va1 >= 0.5f);
        va = sa ? 0.0f : va1;

        // pack 32 bf16 spikes (0.0 / 1.0) and store 64B
        unsigned one = sa ? 0x3F80u : 0u;
        unsigned words[16];
        #pragma unroll
        for (int dp = 0; dp < 16; ++dp) {
            unsigned lo = ((kmask >> (2 * dp)) & 1u) ? one : 0u;
            unsigned hi = ((kmask >> (2 * dp + 1)) & 1u) ? one : 0u;
            words[dp] = lo | (hi << 16);
        }
        __nv_bfloat16* dst = g_xoneT + ((size_t)(t * B_ + b) * N_ + n) * C_ + h * 32;
        #pragma unroll
        for (int qd = 0; qd < 4; ++qd) {
            uint4 u = make_uint4(words[qd * 4 + 0], words[qd * 4 + 1],
                                 words[qd * 4 + 2], words[qd * 4 + 3]);
            *(uint4*)(dst + qd * 8) = u;
        }
    }
}

// ---------------------------------------------------------------------------
// K3: projection GEMM via mma.sync bf16: 3 split segments (binary B is exact
// in bf16). +bias +BN folded. Writes plin (= g_qlin reuse).
// grid (ntile=8, mhalf=2, batch=128), 128 threads.
// ---------------------------------------------------------------------------
__global__ void __launch_bounds__(128) hmma_p_kernel(
    const float* __restrict__ p_b, const float* __restrict__ p_g,
    const float* __restrict__ p_be, const float* __restrict__ p_m,
    const float* __restrict__ p_v)
{
    __shared__ __nv_bfloat16 As[2][128][40];
    __shared__ __nv_bfloat16 Bs[2][128][40];

    const int tid    = threadIdx.x;
    const int lane   = tid & 31;
    const int wid    = tid >> 5;
    const int warp_m = wid >> 1;
    const int warp_n = wid & 1;
    const int ntile  = blockIdx.x;
    const int mhalf  = blockIdx.y;
    const int batch  = blockIdx.z;

    const __nv_bfloat16* Ab = g_wsplit + ((size_t)(2 * 3) * C_ + mhalf * 128) * C_;
    const __nv_bfloat16* Bb = g_xoneT + ((size_t)batch * N_ + ntile * 128) * C_;

    auto load_tiles = [&](int buf, int seg, int kc) {
        const __nv_bfloat16* Ag = Ab + (size_t)seg * C_ * C_ + kc * 32;
        const __nv_bfloat16* Bg = Bb + kc * 32;
        #pragma unroll
        for (int i = 0; i < 4; ++i) {
            int cid = tid + i * 128;
            int row = cid >> 2, c8 = (cid & 3) * 8;
            cpa16(smem_u32(&As[buf][row][c8]), Ag + (size_t)row * C_ + c8);
            cpa16(smem_u32(&Bs[buf][row][c8]), Bg + (size_t)row * C_ + c8);
        }
    };

    float acc[4][8][4];
    #pragma unroll
    for (int mt = 0; mt < 4; ++mt)
        #pragma unroll
        for (int nt = 0; nt < 8; ++nt)
            #pragma unroll
            for (int c = 0; c < 4; ++c)
                acc[mt][nt][c] = 0.0f;

    load_tiles(0, 0, 0);
    CP_COMMIT();

    #pragma unroll 1
    for (int it = 0; it < 24; ++it) {
        const int buf = it & 1;
        if (it < 23) {
            load_tiles(buf ^ 1, (it + 1) >> 3, (it + 1) & 7);
            CP_COMMIT();
            CP_WAIT1();
        } else {
            CP_WAIT0();
        }
        __syncthreads();

        #pragma unroll
        for (int ks = 0; ks < 2; ++ks) {
            uint32_t af[4][4];
            #pragma unroll
            for (int mt = 0; mt < 4; ++mt) {
                int arow = warp_m * 64 + mt * 16 + (lane & 15);
                int acol = ks * 16 + (lane >> 4) * 8;
                ldsm_x4(af[mt][0], af[mt][1], af[mt][2], af[mt][3],
                        smem_u32(&As[buf][arow][acol]));
            }
            uint32_t bfr[8][2];
            #pragma unroll
            for (int g = 0; g < 4; ++g) {
                int brow = warp_n * 64 + g * 16 + (lane & 7) + ((lane >> 4) & 1) * 8;
                int bcol = ks * 16 + ((lane >> 3) & 1) * 8;
                uint32_t r0, r1, r2, r3;
                ldsm_x4(r0, r1, r2, r3, smem_u32(&Bs[buf][brow][bcol]));
                bfr[g * 2 + 0][0] = r0;  bfr[g * 2 + 0][1] = r1;
                bfr[g * 2 + 1][0] = r2;  bfr[g * 2 + 1][1] = r3;
            }
            #pragma unroll
            for (int mt = 0; mt < 4; ++mt)
                #pragma unroll
                for (int nt = 0; nt < 8; ++nt)
                    mma_bf16(acc[mt][nt], af[mt], bfr[nt]);
        }
        __syncthreads();
    }

    // epilogue: (y + bias)*inv + sh = y*inv + (bias*inv + sh); store plin
    const int n0 = ntile * 128 + warp_n * 64 + (lane & 3) * 2;
    #pragma unroll
    for (int mt = 0; mt < 4; ++mt) {
        #pragma unroll
        for (int h = 0; h < 2; ++h) {
            const int o = mhalf * 128 + warp_m * 64 + mt * 16 + (lane >> 2) + h * 8;
            const float iv = p_g[o] / sqrtf(p_v[o] + EPS_);
            const float sh = (p_be[o] - p_m[o] * iv) + p_b[o] * iv;
            float* orow = g_qlin + ((size_t)batch * C_ + o) * N_;
            #pragma unroll
            for (int nt = 0; nt < 8; ++nt) {
                float2 r;
                r.x = acc[mt][nt][h * 2 + 0] * iv + sh;
                r.y = acc[mt][nt][h * 2 + 1] * iv + sh;
                *(float2*)(orow + n0 + nt * 8) = r;
            }
        }
    }
}

// ---------------------------------------------------------------------------
// K4: final LIF over T (streaming, float4 per thread).
// ---------------------------------------------------------------------------
__global__ void __launch_bounds__(256) lif_out_kernel(float* __restrict__ out)
{
    const size_t i = ((size_t)blockIdx.x * 256 + threadIdx.x) * 4;
    const size_t stride = (size_t)B_ * C_ * N_;
    float4 v = make_float4(0.f, 0.f, 0.f, 0.f);
    #pragma unroll
    for (int t = 0; t < T_; ++t) {
        float4 y = *(const float4*)(g_qlin + (size_t)t * stride + i);
        float4 s;
        float v1;
        v1 = v.x + (y.x - v.x) * 0.5f; s.x = (v1 >= 1.0f) ? 1.0f : 0.0f; v.x = (v1 >= 1.0f) ? 0.0f : v1;
        v1 = v.y + (y.y - v.y) * 0.5f; s.y = (v1 >= 1.0f) ? 1.0f : 0.0f; v.y = (v1 >= 1.0f) ? 0.0f : v1;
        v1 = v.z + (y.z - v.z) * 0.5f; s.z = (v1 >= 1.0f) ? 1.0f : 0.0f; v.z = (v1 >= 1.0f) ? 0.0f : v1;
        v1 = v.w + (y.w - v.w) * 0.5f; s.w = (v1 >= 1.0f) ? 1.0f : 0.0f; v.w = (v1 >= 1.0f) ? 0.0f : v1;
        *(float4*)(out + (size_t)t * stride + i) = s;
    }
}

// ---------------------------------------------------------------------------
extern "C" void kernel_launch(void* const* d_in, const int* in_sizes, int n_in,
                              void* d_out, int out_size)
{
    (void)in_sizes; (void)n_in; (void)out_size;
    const float* x    = (const float*)d_in[0];
    const float* q_w  = (const float*)d_in[1];
    const float* q_g  = (const float*)d_in[2];
    const float* q_be = (const float*)d_in[3];
    const float* q_m  = (const float*)d_in[4];
    const float* q_v  = (const float*)d_in[5];
    const float* k_w  = (const float*)d_in[6];
    const float* k_g  = (const float*)d_in[7];
    const float* k_be = (const float*)d_in[8];
    const float* k_m  = (const float*)d_in[9];
    const float* k_v  = (const float*)d_in[10];
    const float* p_w  = (const float*)d_in[11];
    const float* p_b  = (const float*)d_in[12];
    const float* p_g  = (const float*)d_in[13];
    const float* p_be = (const float*)d_in[14];
    const float* p_m  = (const float*)d_in[15];
    const float* p_v  = (const float*)d_in[16];
    float* out = (float*)d_out;

    split_w_kernel<<<256, 256>>>(q_w, k_w, p_w);

    dim3 gs(N_ / 128, C_ / 32, NBATCH);
    split_x_kernel<<<gs, 256>>>(x);

    dim3 g1(8, 4, NBATCH);
    hmma_qk_kernel<<<g1, 128>>>(q_g, q_be, q_m, q_v, k_g, k_be, k_m, k_v);

    dim3 g2(N_ / 256, 8, B_);
    lif_attn_kernel<<<g2, 256>>>();

    dim3 g3(8, 2, NBATCH);
    hmma_p_kernel<<<g3, 128>>>(p_b, p_g, p_be, p_m, p_v);

    lif_out_kernel<<<(B_ * C_ * N_) / 4 / 256, 256>>>(out);
}